// round 1
// baseline (speedup 1.0000x reference)
#include <cuda_runtime.h>
#include <math.h>

// Problem constants
#define BB   2
#define TT   2048
#define EMBD 2048
#define NHE  16
#define NGR  4
#define HDIM 128
#define MROWS (BB*TT)          // 4096 flattened (b,t) rows

// Scratch (allocation-free: __device__ globals)
__device__ float g_q[MROWS * EMBD];        // 32 MB  (b,t, h*128+d)
__device__ float g_k[MROWS * NGR * HDIM];  // 8 MB   (b,t, g*128+d)
__device__ float g_v[MROWS * NGR * HDIM];  // 8 MB
__device__ float g_attn[MROWS * EMBD];     // 32 MB  attention output, (b,t, h*128+d)

// ---------------------------------------------------------------------------
// SGEMM  C[M,N] = A[M,K] * B[N,K]^T      (both operands K-major, fp32)
// 128x128 block, BK=8, 256 threads, 8x8 per thread, double-buffered smem.
// Thread tile is split cyclically (cols tx*4 and 64+tx*4) so LDS.128 reads
// hit banks 4*tx -> conflict-free per 8-lane phase.
// ---------------------------------------------------------------------------
__global__ __launch_bounds__(256) void sgemm_nt(const float* __restrict__ A,
                                                const float* __restrict__ Bm,
                                                float* __restrict__ C,
                                                int M, int N, int K)
{
    __shared__ float As[2][8][132];
    __shared__ float Bs[2][8][132];

    const int tid = threadIdx.x;
    const int bm = blockIdx.y * 128;
    const int bn = blockIdx.x * 128;

    const int lrow = tid >> 1;          // 0..127
    const int lcol = (tid & 1) * 4;     // 0 or 4
    const int tx = tid & 15;
    const int ty = tid >> 4;

    const float* Aptr = A + (size_t)(bm + lrow) * K + lcol;
    const float* Bptr = Bm + (size_t)(bn + lrow) * K + lcol;

    float acc[8][8];
#pragma unroll
    for (int i = 0; i < 8; ++i)
#pragma unroll
        for (int j = 0; j < 8; ++j) acc[i][j] = 0.f;

    const int KT = K >> 3;

    // prologue: tile 0
    float4 pa = *(const float4*)(Aptr);
    float4 pb = *(const float4*)(Bptr);
    As[0][lcol + 0][lrow] = pa.x;
    As[0][lcol + 1][lrow] = pa.y;
    As[0][lcol + 2][lrow] = pa.z;
    As[0][lcol + 3][lrow] = pa.w;
    Bs[0][lcol + 0][lrow] = pb.x;
    Bs[0][lcol + 1][lrow] = pb.y;
    Bs[0][lcol + 2][lrow] = pb.z;
    Bs[0][lcol + 3][lrow] = pb.w;
    __syncthreads();

    int buf = 0;
    for (int kt = 0; kt < KT; ++kt) {
        if (kt + 1 < KT) {
            pa = *(const float4*)(Aptr + (size_t)(kt + 1) * 8);
            pb = *(const float4*)(Bptr + (size_t)(kt + 1) * 8);
        }
#pragma unroll
        for (int k = 0; k < 8; ++k) {
            float4 a0 = *(const float4*)&As[buf][k][ty * 4];
            float4 a1 = *(const float4*)&As[buf][k][64 + ty * 4];
            float4 b0 = *(const float4*)&Bs[buf][k][tx * 4];
            float4 b1 = *(const float4*)&Bs[buf][k][64 + tx * 4];
            float av[8] = {a0.x, a0.y, a0.z, a0.w, a1.x, a1.y, a1.z, a1.w};
            float bv[8] = {b0.x, b0.y, b0.z, b0.w, b1.x, b1.y, b1.z, b1.w};
#pragma unroll
            for (int i = 0; i < 8; ++i)
#pragma unroll
                for (int j = 0; j < 8; ++j)
                    acc[i][j] += av[i] * bv[j];
        }
        if (kt + 1 < KT) {
            buf ^= 1;
            As[buf][lcol + 0][lrow] = pa.x;
            As[buf][lcol + 1][lrow] = pa.y;
            As[buf][lcol + 2][lrow] = pa.z;
            As[buf][lcol + 3][lrow] = pa.w;
            Bs[buf][lcol + 0][lrow] = pb.x;
            Bs[buf][lcol + 1][lrow] = pb.y;
            Bs[buf][lcol + 2][lrow] = pb.z;
            Bs[buf][lcol + 3][lrow] = pb.w;
            __syncthreads();
        }
    }

    // epilogue: rows (rh*64 + ty*4 + u), cols (ch*64 + tx*4 + v)
#pragma unroll
    for (int rh = 0; rh < 2; ++rh)
#pragma unroll
        for (int u = 0; u < 4; ++u) {
            int i = rh * 4 + u;
            int row = bm + rh * 64 + ty * 4 + u;
            float* crow = C + (size_t)row * N + bn;
#pragma unroll
            for (int ch = 0; ch < 2; ++ch) {
                float4 w;
                w.x = acc[i][ch * 4 + 0];
                w.y = acc[i][ch * 4 + 1];
                w.z = acc[i][ch * 4 + 2];
                w.w = acc[i][ch * 4 + 3];
                *(float4*)(crow + ch * 64 + tx * 4) = w;
            }
        }
}

// ---------------------------------------------------------------------------
// RoPE (interleaved pairs), applied in place to q or k buffers.
// buf layout: row-major [MROWS, heads*128]; pair i uses cols (2i, 2i+1).
// ---------------------------------------------------------------------------
__global__ void rope_kernel(float* __restrict__ buf, int heads)
{
    int idx = blockIdx.x * blockDim.x + threadIdx.x;
    int total = MROWS * heads * 64;
    if (idx >= total) return;
    int i = idx & 63;                 // half-dim index 0..63
    int h = (idx >> 6) % heads;
    int row = idx / (heads * 64);
    int t = row % TT;

    // inv_freq = 10000^(-2i/128) = 2^(-i * log2(10000)/64)
    float f = exp2f(-(float)i * (13.287712379549449f / 64.0f));
    float ang = (float)t * f;
    float s, c;
    sincosf(ang, &s, &c);

    float* p = buf + (size_t)row * heads * HDIM + h * HDIM + 2 * i;
    float x1 = p[0], x2 = p[1];
    p[0] = x1 * c - x2 * s;
    p[1] = x1 * s + x2 * c;
}

// ---------------------------------------------------------------------------
// Fused causal flash attention, fp32. 64x64 tiles, HD=128, 256 threads.
// Thread (ty=tid/16, tx=tid&15). S tile: rows ty+16r, cols tx+16c (cyclic ->
// conflict-free LDS.128 at row stride 132). O: rows ty+16r, cols tx*4 & 64+tx*4.
// grid = (T/64, NH, B)
// ---------------------------------------------------------------------------
#define FLASH_SMEM ((3 * 64 * 132 + 64 * 68) * 4)

__global__ __launch_bounds__(256) void flash_attn()
{
    extern __shared__ float sm[];
    float* sQ = sm;                  // [64][132]
    float* sK = sQ + 64 * 132;       // [64][132]
    float* sV = sK + 64 * 132;       // [64][132]
    float* sP = sV + 64 * 132;       // [64][68]

    const int tid = threadIdx.x;
    const int tx = tid & 15;
    const int ty = tid >> 4;
    const int qt = blockIdx.x;
    const int h = blockIdx.y;
    const int b = blockIdx.z;
    const int g = h >> 2;            // h / HPG
    const int qbase = qt * 64;
    const size_t rowbase = (size_t)b * TT;

    // load Q tile (fully coalesced: 32 lanes cover one 128-float row)
    for (int idx = tid; idx < 64 * 32; idx += 256) {
        int r = idx >> 5, c4 = (idx & 31) * 4;
        *(float4*)&sQ[r * 132 + c4] =
            *(const float4*)&g_q[(rowbase + qbase + r) * EMBD + h * HDIM + c4];
    }

    float m[4], l[4], o[4][8];
#pragma unroll
    for (int r = 0; r < 4; ++r) {
        m[r] = -1e30f;
        l[r] = 0.f;
#pragma unroll
        for (int j = 0; j < 8; ++j) o[r][j] = 0.f;
    }
    const float scale = 0.08838834764831845f;  // 1/sqrt(128)

    for (int kt = 0; kt <= qt; ++kt) {
        __syncthreads();  // prev-iter PV done (and Q visible on iter 0)
        int kbase = kt * 64;
        for (int idx = tid; idx < 64 * 32; idx += 256) {
            int r = idx >> 5, c4 = (idx & 31) * 4;
            size_t src = (rowbase + kbase + r) * (NGR * HDIM) + g * HDIM + c4;
            *(float4*)&sK[r * 132 + c4] = *(const float4*)&g_k[src];
            *(float4*)&sV[r * 132 + c4] = *(const float4*)&g_v[src];
        }
        __syncthreads();

        // S = Q K^T  (4x4 per thread)
        float s[4][4];
#pragma unroll
        for (int r = 0; r < 4; ++r)
#pragma unroll
            for (int c = 0; c < 4; ++c) s[r][c] = 0.f;

#pragma unroll 4
        for (int d4 = 0; d4 < 32; ++d4) {
            float4 qv[4], kv[4];
#pragma unroll
            for (int r = 0; r < 4; ++r)
                qv[r] = *(const float4*)&sQ[(ty + 16 * r) * 132 + d4 * 4];
#pragma unroll
            for (int c = 0; c < 4; ++c)
                kv[c] = *(const float4*)&sK[(tx + 16 * c) * 132 + d4 * 4];
#pragma unroll
            for (int r = 0; r < 4; ++r)
#pragma unroll
                for (int c = 0; c < 4; ++c) {
                    s[r][c] += qv[r].x * kv[c].x;
                    s[r][c] += qv[r].y * kv[c].y;
                    s[r][c] += qv[r].z * kv[c].z;
                    s[r][c] += qv[r].w * kv[c].w;
                }
        }

        // scale + causal mask (only diagonal tile can mask)
        const bool diag = (kt == qt);
#pragma unroll
        for (int r = 0; r < 4; ++r)
#pragma unroll
            for (int c = 0; c < 4; ++c) {
                float sv = s[r][c] * scale;
                if (diag && (kbase + tx + 16 * c) > (qbase + ty + 16 * r))
                    sv = -1e30f;
                s[r][c] = sv;
            }

        // online softmax (row stats reduced across the 16 tx lanes)
#pragma unroll
        for (int r = 0; r < 4; ++r) {
            float tm = fmaxf(fmaxf(s[r][0], s[r][1]), fmaxf(s[r][2], s[r][3]));
#pragma unroll
            for (int off = 8; off >= 1; off >>= 1)
                tm = fmaxf(tm, __shfl_xor_sync(0xffffffffu, tm, off));
            float mn = fmaxf(m[r], tm);
            float alpha = __expf(m[r] - mn);
            float rs = 0.f;
#pragma unroll
            for (int c = 0; c < 4; ++c) {
                float p = __expf(s[r][c] - mn);
                sP[(ty + 16 * r) * 68 + tx + 16 * c] = p;
                rs += p;
            }
#pragma unroll
            for (int off = 8; off >= 1; off >>= 1)
                rs += __shfl_xor_sync(0xffffffffu, rs, off);
            l[r] = l[r] * alpha + rs;
            m[r] = mn;
#pragma unroll
            for (int j = 0; j < 8; ++j) o[r][j] *= alpha;
        }
        __syncthreads();  // sP visible

        // O += P V   (rows ty+16r; d cols tx*4 and 64+tx*4 -> banks 4*tx)
#pragma unroll 4
        for (int j = 0; j < 64; ++j) {
            float4 v0 = *(const float4*)&sV[j * 132 + tx * 4];
            float4 v1 = *(const float4*)&sV[j * 132 + 64 + tx * 4];
#pragma unroll
            for (int r = 0; r < 4; ++r) {
                float p = sP[(ty + 16 * r) * 68 + j];
                o[r][0] += p * v0.x;
                o[r][1] += p * v0.y;
                o[r][2] += p * v0.z;
                o[r][3] += p * v0.w;
                o[r][4] += p * v1.x;
                o[r][5] += p * v1.y;
                o[r][6] += p * v1.z;
                o[r][7] += p * v1.w;
            }
        }
    }

    // epilogue: normalize and store to g_attn[(b,t), h*128+d]
#pragma unroll
    for (int r = 0; r < 4; ++r) {
        float inv = 1.f / l[r];
        int row = qbase + ty + 16 * r;
        float* dst = &g_attn[(rowbase + row) * EMBD + h * HDIM];
        float4 w0, w1;
        w0.x = o[r][0] * inv; w0.y = o[r][1] * inv;
        w0.z = o[r][2] * inv; w0.w = o[r][3] * inv;
        w1.x = o[r][4] * inv; w1.y = o[r][5] * inv;
        w1.z = o[r][6] * inv; w1.w = o[r][7] * inv;
        *(float4*)&dst[tx * 4] = w0;
        *(float4*)&dst[64 + tx * 4] = w1;
    }
}

// ---------------------------------------------------------------------------
// Launch
// ---------------------------------------------------------------------------
extern "C" void kernel_launch(void* const* d_in, const int* in_sizes, int n_in,
                              void* d_out, int out_size)
{
    const float* x  = (const float*)d_in[0];
    const float* Wq = (const float*)d_in[1];
    const float* Wk = (const float*)d_in[2];
    const float* Wv = (const float*)d_in[3];
    const float* Wo = (const float*)d_in[4];

    float *q, *k, *v, *attn;
    cudaGetSymbolAddress((void**)&q, g_q);
    cudaGetSymbolAddress((void**)&k, g_k);
    cudaGetSymbolAddress((void**)&v, g_v);
    cudaGetSymbolAddress((void**)&attn, g_attn);

    // projections: C = A * W^T
    sgemm_nt<<<dim3(16, 32), 256>>>(x, Wq, q, MROWS, EMBD, EMBD);
    sgemm_nt<<<dim3(4, 32), 256>>>(x, Wk, k, MROWS, NGR * HDIM, EMBD);
    sgemm_nt<<<dim3(4, 32), 256>>>(x, Wv, v, MROWS, NGR * HDIM, EMBD);

    // RoPE on q and k
    rope_kernel<<<(MROWS * NHE * 64) / 256, 256>>>(q, NHE);
    rope_kernel<<<(MROWS * NGR * 64) / 256, 256>>>(k, NGR);

    // fused causal attention
    cudaFuncSetAttribute(flash_attn, cudaFuncAttributeMaxDynamicSharedMemorySize,
                         FLASH_SMEM);
    flash_attn<<<dim3(TT / 64, NHE, BB), 256, FLASH_SMEM>>>();

    // output projection
    sgemm_nt<<<dim3(16, 32), 256>>>(attn, Wo, (float*)d_out, MROWS, EMBD, EMBD);
}

// round 7
// speedup vs baseline: 1.2356x; 1.2356x over previous
#include <cuda_runtime.h>
#include <math.h>
#include <cstdint>

// Problem constants
#define BB   2
#define TT   2048
#define EMBD 2048
#define NHE  16
#define NGR  4
#define HDIM 128
#define MROWS (BB*TT)          // 4096 flattened (b,t) rows

// Scratch (allocation-free: __device__ globals)
__device__ float g_q[MROWS * EMBD];
__device__ float g_k[MROWS * NGR * HDIM];
__device__ float g_v[MROWS * NGR * HDIM];
__device__ float g_attn[MROWS * EMBD];

// ===========================================================================
// helpers
// ===========================================================================
__device__ __forceinline__ uint32_t smem_u32(const void* p) {
    uint32_t a;
    asm("{ .reg .u64 t; cvta.to.shared.u64 t, %1; cvt.u32.u64 %0, t; }"
        : "=r"(a) : "l"(p));
    return a;
}

#define CP_ASYNC16(dst_u32, src_ptr) \
    asm volatile("cp.async.cg.shared.global [%0], [%1], 16;" \
        :: "r"(dst_u32), "l"(src_ptr))
#define CP_COMMIT() asm volatile("cp.async.commit_group;" ::: "memory")
#define CP_WAIT(n)  asm volatile("cp.async.wait_group %0;" :: "n"(n) : "memory")

// m16n8k8 tf32 mma (sm_80+, no arch suffix needed)
__device__ __forceinline__ void mma_tf32(float* c, const uint32_t* a,
                                         const uint32_t* b) {
    asm volatile(
        "mma.sync.aligned.m16n8k8.row.col.f32.tf32.tf32.f32 "
        "{%0,%1,%2,%3}, {%4,%5,%6,%7}, {%8,%9}, {%0,%1,%2,%3};\n"
        : "+f"(c[0]), "+f"(c[1]), "+f"(c[2]), "+f"(c[3])
        : "r"(a[0]), "r"(a[1]), "r"(a[2]), "r"(a[3]), "r"(b[0]), "r"(b[1]));
}

// ===========================================================================
// TF32 tensor-core GEMM with 3xTF32 compensation:
//   C[M,N] = A[M,K] * B[N,K]^T   (fp32 in/out, ~fp32 accuracy)
// 128x128 CTA tile, BK=32, 256 threads = 8 warps (2m x 4n), warp tile 64x32.
// cp.async double-buffered smem holds RAW fp32 tiles; hi/lo tf32 split happens
// at fragment-load time. D += Ah*Bh + Al*Bh + Ah*Bl.
// smem rows padded to 36 floats: fragment LDS banks = (4g+tig) -> conflict-free;
// 16B alignment preserved (36*4 = 144B).
// grid = (N/128, M/128).
// ===========================================================================
#define BK     32
#define LDS_W  36
#define A_FLOATS (128 * LDS_W)            // 4608 floats
#define BUF_FLOATS (2 * A_FLOATS)         // A + B per buffer
#define GEMM_SMEM (2 * BUF_FLOATS * 4)    // 73728 bytes

__global__ __launch_bounds__(256) void gemm_tf32(const float* __restrict__ A,
                                                 const float* __restrict__ Bm,
                                                 float* __restrict__ C,
                                                 int M, int N, int K)
{
    extern __shared__ float smem[];
    const uint32_t sb = smem_u32(smem);
    const int tid = threadIdx.x;
    const int wid = tid >> 5;
    const int lane = tid & 31;
    const int g = lane >> 2;          // groupID 0..7
    const int tig = lane & 3;         // thread in group
    const int wm = wid & 1;           // warp m index (2)
    const int wn = wid >> 1;          // warp n index (4)
    const int bm = blockIdx.y * 128;
    const int bn = blockIdx.x * 128;

    float acc[4][4][4];
#pragma unroll
    for (int i = 0; i < 4; ++i)
#pragma unroll
        for (int j = 0; j < 4; ++j)
#pragma unroll
            for (int v = 0; v < 4; ++v) acc[i][j][v] = 0.f;

    const int KT = K / BK;

    // per-thread load slots: 1024 float4 slots per matrix, 4 per thread
    // slot -> row = slot>>3, kc = (slot&7)*4
    auto issue_tile = [&](int kt, int buf) {
        const int k0 = kt * BK;
        const uint32_t base = sb + (uint32_t)buf * BUF_FLOATS * 4;
#pragma unroll
        for (int i = 0; i < 4; ++i) {
            int slot = tid + i * 256;
            int row = slot >> 3;
            int kc = (slot & 7) << 2;
            uint32_t doff = (uint32_t)(row * LDS_W + kc) * 4;
            CP_ASYNC16(base + doff, &A[(size_t)(bm + row) * K + k0 + kc]);
            CP_ASYNC16(base + (uint32_t)A_FLOATS * 4 + doff,
                       &Bm[(size_t)(bn + row) * K + k0 + kc]);
        }
        CP_COMMIT();
    };

    issue_tile(0, 0);

    for (int kt = 0; kt < KT; ++kt) {
        const int buf = kt & 1;
        if (kt + 1 < KT) {
            issue_tile(kt + 1, buf ^ 1);
            CP_WAIT(1);
        } else {
            CP_WAIT(0);
        }
        __syncthreads();

        const float* As = smem + buf * BUF_FLOATS;
        const float* Bs = As + A_FLOATS;

#pragma unroll
        for (int kk = 0; kk < 4; ++kk) {
            const int k0 = kk * 8;
            // load + split A fragments (m16n8k8 layout)
            uint32_t ah[4][4], al[4][4];
#pragma unroll
            for (int mf = 0; mf < 4; ++mf) {
                const int m = wm * 64 + mf * 16 + g;
#pragma unroll
                for (int j = 0; j < 4; ++j) {
                    int row = m + (j & 1) * 8;
                    int kc = k0 + tig + (j >> 1) * 4;
                    float v = As[row * LDS_W + kc];
                    uint32_t hb = __float_as_uint(v) & 0xFFFFE000u;
                    ah[mf][j] = hb;
                    al[mf][j] = __float_as_uint(v - __uint_as_float(hb));
                }
            }
            // load + split B fragments
            uint32_t bh[4][2], bl[4][2];
#pragma unroll
            for (int nf = 0; nf < 4; ++nf) {
                const int n = wn * 32 + nf * 8 + g;
#pragma unroll
                for (int j = 0; j < 2; ++j) {
                    int kc = k0 + tig + j * 4;
                    float v = Bs[n * LDS_W + kc];
                    uint32_t hb = __float_as_uint(v) & 0xFFFFE000u;
                    bh[nf][j] = hb;
                    bl[nf][j] = __float_as_uint(v - __uint_as_float(hb));
                }
            }
            // hi*hi
#pragma unroll
            for (int mf = 0; mf < 4; ++mf)
#pragma unroll
                for (int nf = 0; nf < 4; ++nf)
                    mma_tf32(acc[mf][nf], ah[mf], bh[nf]);
            // lo*hi
#pragma unroll
            for (int mf = 0; mf < 4; ++mf)
#pragma unroll
                for (int nf = 0; nf < 4; ++nf)
                    mma_tf32(acc[mf][nf], al[mf], bh[nf]);
            // hi*lo
#pragma unroll
            for (int mf = 0; mf < 4; ++mf)
#pragma unroll
                for (int nf = 0; nf < 4; ++nf)
                    mma_tf32(acc[mf][nf], ah[mf], bl[nf]);
        }
        __syncthreads();
    }

    // epilogue: c0,c1 -> (row, col..col+1); c2,c3 -> (row+8, col..col+1)
#pragma unroll
    for (int mf = 0; mf < 4; ++mf) {
#pragma unroll
        for (int nf = 0; nf < 4; ++nf) {
            int row = bm + wm * 64 + mf * 16 + g;
            int col = bn + wn * 32 + nf * 8 + tig * 2;
            float2 w0 = make_float2(acc[mf][nf][0], acc[mf][nf][1]);
            float2 w1 = make_float2(acc[mf][nf][2], acc[mf][nf][3]);
            *(float2*)&C[(size_t)row * N + col] = w0;
            *(float2*)&C[(size_t)(row + 8) * N + col] = w1;
        }
    }
}

// ---------------------------------------------------------------------------
// RoPE (interleaved pairs), in place.
// ---------------------------------------------------------------------------
__global__ void rope_kernel(float* __restrict__ buf, int heads)
{
    int idx = blockIdx.x * blockDim.x + threadIdx.x;
    int total = MROWS * heads * 64;
    if (idx >= total) return;
    int i = idx & 63;
    int h = (idx >> 6) % heads;
    int row = idx / (heads * 64);
    int t = row % TT;

    float f = exp2f(-(float)i * (13.287712379549449f / 64.0f));
    float ang = (float)t * f;
    float s, c;
    sincosf(ang, &s, &c);

    float* p = buf + (size_t)row * heads * HDIM + h * HDIM + 2 * i;
    float x1 = p[0], x2 = p[1];
    p[0] = x1 * c - x2 * s;
    p[1] = x1 * s + x2 * c;
}

// ---------------------------------------------------------------------------
// Fused causal flash attention, fp32 SIMT (unchanged from round 1, passing).
// ---------------------------------------------------------------------------
#define FLASH_SMEM ((3 * 64 * 132 + 64 * 68) * 4)

__global__ __launch_bounds__(256) void flash_attn()
{
    extern __shared__ float sm[];
    float* sQ = sm;
    float* sK = sQ + 64 * 132;
    float* sV = sK + 64 * 132;
    float* sP = sV + 64 * 132;

    const int tid = threadIdx.x;
    const int tx = tid & 15;
    const int ty = tid >> 4;
    const int qt = blockIdx.x;
    const int h = blockIdx.y;
    const int b = blockIdx.z;
    const int g = h >> 2;
    const int qbase = qt * 64;
    const size_t rowbase = (size_t)b * TT;

    for (int idx = tid; idx < 64 * 32; idx += 256) {
        int r = idx >> 5, c4 = (idx & 31) * 4;
        *(float4*)&sQ[r * 132 + c4] =
            *(const float4*)&g_q[(rowbase + qbase + r) * EMBD + h * HDIM + c4];
    }

    float m[4], l[4], o[4][8];
#pragma unroll
    for (int r = 0; r < 4; ++r) {
        m[r] = -1e30f;
        l[r] = 0.f;
#pragma unroll
        for (int j = 0; j < 8; ++j) o[r][j] = 0.f;
    }
    const float scale = 0.08838834764831845f;

    for (int kt = 0; kt <= qt; ++kt) {
        __syncthreads();
        int kbase = kt * 64;
        for (int idx = tid; idx < 64 * 32; idx += 256) {
            int r = idx >> 5, c4 = (idx & 31) * 4;
            size_t src = (rowbase + kbase + r) * (NGR * HDIM) + g * HDIM + c4;
            *(float4*)&sK[r * 132 + c4] = *(const float4*)&g_k[src];
            *(float4*)&sV[r * 132 + c4] = *(const float4*)&g_v[src];
        }
        __syncthreads();

        float s[4][4];
#pragma unroll
        for (int r = 0; r < 4; ++r)
#pragma unroll
            for (int c = 0; c < 4; ++c) s[r][c] = 0.f;

#pragma unroll 4
        for (int d4 = 0; d4 < 32; ++d4) {
            float4 qv[4], kv[4];
#pragma unroll
            for (int r = 0; r < 4; ++r)
                qv[r] = *(const float4*)&sQ[(ty + 16 * r) * 132 + d4 * 4];
#pragma unroll
            for (int c = 0; c < 4; ++c)
                kv[c] = *(const float4*)&sK[(tx + 16 * c) * 132 + d4 * 4];
#pragma unroll
            for (int r = 0; r < 4; ++r)
#pragma unroll
                for (int c = 0; c < 4; ++c) {
                    s[r][c] += qv[r].x * kv[c].x;
                    s[r][c] += qv[r].y * kv[c].y;
                    s[r][c] += qv[r].z * kv[c].z;
                    s[r][c] += qv[r].w * kv[c].w;
                }
        }

        const bool diag = (kt == qt);
#pragma unroll
        for (int r = 0; r < 4; ++r)
#pragma unroll
            for (int c = 0; c < 4; ++c) {
                float sv = s[r][c] * scale;
                if (diag && (kbase + tx + 16 * c) > (qbase + ty + 16 * r))
                    sv = -1e30f;
                s[r][c] = sv;
            }

#pragma unroll
        for (int r = 0; r < 4; ++r) {
            float tm = fmaxf(fmaxf(s[r][0], s[r][1]), fmaxf(s[r][2], s[r][3]));
#pragma unroll
            for (int off = 8; off >= 1; off >>= 1)
                tm = fmaxf(tm, __shfl_xor_sync(0xffffffffu, tm, off));
            float mn = fmaxf(m[r], tm);
            float alpha = __expf(m[r] - mn);
            float rs = 0.f;
#pragma unroll
            for (int c = 0; c < 4; ++c) {
                float p = __expf(s[r][c] - mn);
                sP[(ty + 16 * r) * 68 + tx + 16 * c] = p;
                rs += p;
            }
#pragma unroll
            for (int off = 8; off >= 1; off >>= 1)
                rs += __shfl_xor_sync(0xffffffffu, rs, off);
            l[r] = l[r] * alpha + rs;
            m[r] = mn;
#pragma unroll
            for (int j = 0; j < 8; ++j) o[r][j] *= alpha;
        }
        __syncthreads();

#pragma unroll 4
        for (int j = 0; j < 64; ++j) {
            float4 v0 = *(const float4*)&sV[j * 132 + tx * 4];
            float4 v1 = *(const float4*)&sV[j * 132 + 64 + tx * 4];
#pragma unroll
            for (int r = 0; r < 4; ++r) {
                float p = sP[(ty + 16 * r) * 68 + j];
                o[r][0] += p * v0.x;
                o[r][1] += p * v0.y;
                o[r][2] += p * v0.z;
                o[r][3] += p * v0.w;
                o[r][4] += p * v1.x;
                o[r][5] += p * v1.y;
                o[r][6] += p * v1.z;
                o[r][7] += p * v1.w;
            }
        }
    }

#pragma unroll
    for (int r = 0; r < 4; ++r) {
        float inv = 1.f / l[r];
        int row = qbase + ty + 16 * r;
        float* dst = &g_attn[(rowbase + row) * EMBD + h * HDIM];
        float4 w0, w1;
        w0.x = o[r][0] * inv; w0.y = o[r][1] * inv;
        w0.z = o[r][2] * inv; w0.w = o[r][3] * inv;
        w1.x = o[r][4] * inv; w1.y = o[r][5] * inv;
        w1.z = o[r][6] * inv; w1.w = o[r][7] * inv;
        *(float4*)&dst[tx * 4] = w0;
        *(float4*)&dst[64 + tx * 4] = w1;
    }
}

// ---------------------------------------------------------------------------
// Launch
// ---------------------------------------------------------------------------
extern "C" void kernel_launch(void* const* d_in, const int* in_sizes, int n_in,
                              void* d_out, int out_size)
{
    const float* x  = (const float*)d_in[0];
    const float* Wq = (const float*)d_in[1];
    const float* Wk = (const float*)d_in[2];
    const float* Wv = (const float*)d_in[3];
    const float* Wo = (const float*)d_in[4];

    float *q, *k, *v, *attn;
    cudaGetSymbolAddress((void**)&q, g_q);
    cudaGetSymbolAddress((void**)&k, g_k);
    cudaGetSymbolAddress((void**)&v, g_v);
    cudaGetSymbolAddress((void**)&attn, g_attn);

    cudaFuncSetAttribute(gemm_tf32, cudaFuncAttributeMaxDynamicSharedMemorySize,
                         GEMM_SMEM);
    cudaFuncSetAttribute(flash_attn, cudaFuncAttributeMaxDynamicSharedMemorySize,
                         FLASH_SMEM);

    // projections: C = A * W^T  (mma.sync tf32, 3x-compensated)
    gemm_tf32<<<dim3(EMBD / 128, MROWS / 128), 256, GEMM_SMEM>>>(x, Wq, q, MROWS, EMBD, EMBD);
    gemm_tf32<<<dim3((NGR * HDIM) / 128, MROWS / 128), 256, GEMM_SMEM>>>(x, Wk, k, MROWS, NGR * HDIM, EMBD);
    gemm_tf32<<<dim3((NGR * HDIM) / 128, MROWS / 128), 256, GEMM_SMEM>>>(x, Wv, v, MROWS, NGR * HDIM, EMBD);

    // RoPE on q and k
    rope_kernel<<<(MROWS * NHE * 64) / 256, 256>>>(q, NHE);
    rope_kernel<<<(MROWS * NGR * 64) / 256, 256>>>(k, NGR);

    // fused causal attention (fp32 SIMT)
    flash_attn<<<dim3(TT / 64, NHE, BB), 256, FLASH_SMEM>>>();

    // output projection
    gemm_tf32<<<dim3(EMBD / 128, MROWS / 128), 256, GEMM_SMEM>>>(attn, Wo, (float*)d_out, MROWS, EMBD, EMBD);
}

// round 9
// speedup vs baseline: 1.4576x; 1.1797x over previous
#include <cuda_runtime.h>
#include <math.h>
#include <cstdint>

// Problem constants
#define BB   2
#define TT   2048
#define EMBD 2048
#define NHE  16
#define NGR  4
#define HDIM 128
#define MROWS (BB*TT)          // 4096 flattened (b,t) rows

// Scratch (allocation-free: __device__ globals)
__device__ float g_q[MROWS * EMBD];
__device__ float g_k[MROWS * NGR * HDIM];
__device__ float g_v[MROWS * NGR * HDIM];
__device__ float g_attn[MROWS * EMBD];

// ===========================================================================
// helpers
// ===========================================================================
__device__ __forceinline__ uint32_t smem_u32(const void* p) {
    uint32_t a;
    asm("{ .reg .u64 t; cvta.to.shared.u64 t, %1; cvt.u32.u64 %0, t; }"
        : "=r"(a) : "l"(p));
    return a;
}

#define CP_ASYNC16(dst_u32, src_ptr) \
    asm volatile("cp.async.cg.shared.global [%0], [%1], 16;" \
        :: "r"(dst_u32), "l"(src_ptr))
#define CP_COMMIT() asm volatile("cp.async.commit_group;" ::: "memory")
#define CP_WAIT(n)  asm volatile("cp.async.wait_group %0;" :: "n"(n) : "memory")

// m16n8k16 bf16 mma (sm_80+, no arch suffix needed)
__device__ __forceinline__ void mma_bf16(float* c, const uint32_t* a,
                                         const uint32_t* b) {
    asm volatile(
        "mma.sync.aligned.m16n8k16.row.col.f32.bf16.bf16.f32 "
        "{%0,%1,%2,%3}, {%4,%5,%6,%7}, {%8,%9}, {%0,%1,%2,%3};\n"
        : "+f"(c[0]), "+f"(c[1]), "+f"(c[2]), "+f"(c[3])
        : "r"(a[0]), "r"(a[1]), "r"(a[2]), "r"(a[3]), "r"(b[0]), "r"(b[1]));
}

// Split a pair of fp32 into packed bf16x2 (hi) + packed bf16x2 (lo residual).
// packed.lo half = element k (x0), packed.hi half = element k+1 (x1).
__device__ __forceinline__ void split_pair(float x0, float x1,
                                           uint32_t& hi, uint32_t& lo) {
    uint32_t h;
    asm("cvt.rn.bf16x2.f32 %0, %1, %2;" : "=r"(h) : "f"(x1), "f"(x0));
    float h0 = __uint_as_float(h << 16);
    float h1 = __uint_as_float(h & 0xFFFF0000u);
    uint32_t l;
    asm("cvt.rn.bf16x2.f32 %0, %1, %2;" : "=r"(l) : "f"(x1 - h1), "f"(x0 - h0));
    hi = h;
    lo = l;
}

// ===========================================================================
// bf16x3 tensor-core GEMM (fp32 accuracy ~2^-17):
//   C[M,N] = A[M,K] * B[N,K]^T   (fp32 in/out)
// 128x128 CTA tile, BK=32, 256 threads = 8 warps (2m x 4n), warp tile 64x32.
// cp.async double-buffered smem holds RAW fp32 tiles; bf16 hi/lo split happens
// at fragment-load time. D += Ah*Bh + Al*Bh + Ah*Bl (m16n8k16 bf16 MMAs).
// smem rows padded to 40 floats: float2 fragment loads hit bank-pairs
// (8g + 2tig) -> conflict-free per half-warp phase; 160B rows keep 16B align.
// grid = (N/128, M/128).
// ===========================================================================
#define BK     32
#define LDS_W  40
#define A_FLOATS (128 * LDS_W)            // 5120 floats
#define BUF_FLOATS (2 * A_FLOATS)         // A + B per buffer
#define GEMM_SMEM (2 * BUF_FLOATS * 4)    // 81920 bytes

__global__ __launch_bounds__(256) void gemm_bf16x3(const float* __restrict__ A,
                                                   const float* __restrict__ Bm,
                                                   float* __restrict__ C,
                                                   int M, int N, int K)
{
    extern __shared__ float smem[];
    const uint32_t sb = smem_u32(smem);
    const int tid = threadIdx.x;
    const int wid = tid >> 5;
    const int lane = tid & 31;
    const int g = lane >> 2;          // groupID 0..7
    const int tig = lane & 3;         // thread in group
    const int wm = wid & 1;           // warp m index (2)
    const int wn = wid >> 1;          // warp n index (4)
    const int bm = blockIdx.y * 128;
    const int bn = blockIdx.x * 128;

    float acc[4][4][4];
#pragma unroll
    for (int i = 0; i < 4; ++i)
#pragma unroll
        for (int j = 0; j < 4; ++j)
#pragma unroll
            for (int v = 0; v < 4; ++v) acc[i][j][v] = 0.f;

    const int KT = K / BK;

    // per-thread load slots: 1024 float4 slots per matrix, 4 per thread
    auto issue_tile = [&](int kt, int buf) {
        const int k0 = kt * BK;
        const uint32_t base = sb + (uint32_t)buf * BUF_FLOATS * 4;
#pragma unroll
        for (int i = 0; i < 4; ++i) {
            int slot = tid + i * 256;
            int row = slot >> 3;
            int kc = (slot & 7) << 2;
            uint32_t doff = (uint32_t)(row * LDS_W + kc) * 4;
            CP_ASYNC16(base + doff, &A[(size_t)(bm + row) * K + k0 + kc]);
            CP_ASYNC16(base + (uint32_t)A_FLOATS * 4 + doff,
                       &Bm[(size_t)(bn + row) * K + k0 + kc]);
        }
        CP_COMMIT();
    };

    issue_tile(0, 0);

    for (int kt = 0; kt < KT; ++kt) {
        const int buf = kt & 1;
        if (kt + 1 < KT) {
            issue_tile(kt + 1, buf ^ 1);
            CP_WAIT(1);
        } else {
            CP_WAIT(0);
        }
        __syncthreads();

        const float* As = smem + buf * BUF_FLOATS;
        const float* Bs = As + A_FLOATS;

#pragma unroll
        for (int kk = 0; kk < 2; ++kk) {
            const int k0 = kk * 16 + 2 * tig;
            // A fragments, m16n8k16: a0=(g,k0..k0+1) a1=(g+8,..) a2=(g,k0+8..) a3=(g+8,k0+8..)
            uint32_t ah[4][4], al[4][4];
#pragma unroll
            for (int mf = 0; mf < 4; ++mf) {
                const int m = wm * 64 + mf * 16 + g;
                float2 p00 = *(const float2*)&As[m * LDS_W + k0];
                float2 p10 = *(const float2*)&As[(m + 8) * LDS_W + k0];
                float2 p01 = *(const float2*)&As[m * LDS_W + k0 + 8];
                float2 p11 = *(const float2*)&As[(m + 8) * LDS_W + k0 + 8];
                split_pair(p00.x, p00.y, ah[mf][0], al[mf][0]);
                split_pair(p10.x, p10.y, ah[mf][1], al[mf][1]);
                split_pair(p01.x, p01.y, ah[mf][2], al[mf][2]);
                split_pair(p11.x, p11.y, ah[mf][3], al[mf][3]);
            }
            // B fragments: b0=(n=g, k0..k0+1), b1=(n=g, k0+8..k0+9)
            uint32_t bh[4][2], bl[4][2];
#pragma unroll
            for (int nf = 0; nf < 4; ++nf) {
                const int n = wn * 32 + nf * 8 + g;
                float2 q0 = *(const float2*)&Bs[n * LDS_W + k0];
                float2 q1 = *(const float2*)&Bs[n * LDS_W + k0 + 8];
                split_pair(q0.x, q0.y, bh[nf][0], bl[nf][0]);
                split_pair(q1.x, q1.y, bh[nf][1], bl[nf][1]);
            }
            // hi*hi
#pragma unroll
            for (int mf = 0; mf < 4; ++mf)
#pragma unroll
                for (int nf = 0; nf < 4; ++nf)
                    mma_bf16(acc[mf][nf], ah[mf], bh[nf]);
            // lo*hi
#pragma unroll
            for (int mf = 0; mf < 4; ++mf)
#pragma unroll
                for (int nf = 0; nf < 4; ++nf)
                    mma_bf16(acc[mf][nf], al[mf], bh[nf]);
            // hi*lo
#pragma unroll
            for (int mf = 0; mf < 4; ++mf)
#pragma unroll
                for (int nf = 0; nf < 4; ++nf)
                    mma_bf16(acc[mf][nf], ah[mf], bl[nf]);
        }
        __syncthreads();
    }

    // epilogue: c0,c1 -> (row, col..col+1); c2,c3 -> (row+8, col..col+1)
#pragma unroll
    for (int mf = 0; mf < 4; ++mf) {
#pragma unroll
        for (int nf = 0; nf < 4; ++nf) {
            int row = bm + wm * 64 + mf * 16 + g;
            int col = bn + wn * 32 + nf * 8 + tig * 2;
            float2 w0 = make_float2(acc[mf][nf][0], acc[mf][nf][1]);
            float2 w1 = make_float2(acc[mf][nf][2], acc[mf][nf][3]);
            *(float2*)&C[(size_t)row * N + col] = w0;
            *(float2*)&C[(size_t)(row + 8) * N + col] = w1;
        }
    }
}

// ---------------------------------------------------------------------------
// RoPE (interleaved pairs), in place.
// ---------------------------------------------------------------------------
__global__ void rope_kernel(float* __restrict__ buf, int heads)
{
    int idx = blockIdx.x * blockDim.x + threadIdx.x;
    int total = MROWS * heads * 64;
    if (idx >= total) return;
    int i = idx & 63;
    int h = (idx >> 6) % heads;
    int row = idx / (heads * 64);
    int t = row % TT;

    float f = exp2f(-(float)i * (13.287712379549449f / 64.0f));
    float ang = (float)t * f;
    float s, c;
    sincosf(ang, &s, &c);

    float* p = buf + (size_t)row * heads * HDIM + h * HDIM + 2 * i;
    float x1 = p[0], x2 = p[1];
    p[0] = x1 * c - x2 * s;
    p[1] = x1 * s + x2 * c;
}

// ---------------------------------------------------------------------------
// Fused causal flash attention, fp32 SIMT (unchanged, passing).
// ---------------------------------------------------------------------------
#define FLASH_SMEM ((3 * 64 * 132 + 64 * 68) * 4)

__global__ __launch_bounds__(256) void flash_attn()
{
    extern __shared__ float sm[];
    float* sQ = sm;
    float* sK = sQ + 64 * 132;
    float* sV = sK + 64 * 132;
    float* sP = sV + 64 * 132;

    const int tid = threadIdx.x;
    const int tx = tid & 15;
    const int ty = tid >> 4;
    const int qt = blockIdx.x;
    const int h = blockIdx.y;
    const int b = blockIdx.z;
    const int g = h >> 2;
    const int qbase = qt * 64;
    const size_t rowbase = (size_t)b * TT;

    for (int idx = tid; idx < 64 * 32; idx += 256) {
        int r = idx >> 5, c4 = (idx & 31) * 4;
        *(float4*)&sQ[r * 132 + c4] =
            *(const float4*)&g_q[(rowbase + qbase + r) * EMBD + h * HDIM + c4];
    }

    float m[4], l[4], o[4][8];
#pragma unroll
    for (int r = 0; r < 4; ++r) {
        m[r] = -1e30f;
        l[r] = 0.f;
#pragma unroll
        for (int j = 0; j < 8; ++j) o[r][j] = 0.f;
    }
    const float scale = 0.08838834764831845f;

    for (int kt = 0; kt <= qt; ++kt) {
        __syncthreads();
        int kbase = kt * 64;
        for (int idx = tid; idx < 64 * 32; idx += 256) {
            int r = idx >> 5, c4 = (idx & 31) * 4;
            size_t src = (rowbase + kbase + r) * (NGR * HDIM) + g * HDIM + c4;
            *(float4*)&sK[r * 132 + c4] = *(const float4*)&g_k[src];
            *(float4*)&sV[r * 132 + c4] = *(const float4*)&g_v[src];
        }
        __syncthreads();

        float s[4][4];
#pragma unroll
        for (int r = 0; r < 4; ++r)
#pragma unroll
            for (int c = 0; c < 4; ++c) s[r][c] = 0.f;

#pragma unroll 4
        for (int d4 = 0; d4 < 32; ++d4) {
            float4 qv[4], kv[4];
#pragma unroll
            for (int r = 0; r < 4; ++r)
                qv[r] = *(const float4*)&sQ[(ty + 16 * r) * 132 + d4 * 4];
#pragma unroll
            for (int c = 0; c < 4; ++c)
                kv[c] = *(const float4*)&sK[(tx + 16 * c) * 132 + d4 * 4];
#pragma unroll
            for (int r = 0; r < 4; ++r)
#pragma unroll
                for (int c = 0; c < 4; ++c) {
                    s[r][c] += qv[r].x * kv[c].x;
                    s[r][c] += qv[r].y * kv[c].y;
                    s[r][c] += qv[r].z * kv[c].z;
                    s[r][c] += qv[r].w * kv[c].w;
                }
        }

        const bool diag = (kt == qt);
#pragma unroll
        for (int r = 0; r < 4; ++r)
#pragma unroll
            for (int c = 0; c < 4; ++c) {
                float sv = s[r][c] * scale;
                if (diag && (kbase + tx + 16 * c) > (qbase + ty + 16 * r))
                    sv = -1e30f;
                s[r][c] = sv;
            }

#pragma unroll
        for (int r = 0; r < 4; ++r) {
            float tm = fmaxf(fmaxf(s[r][0], s[r][1]), fmaxf(s[r][2], s[r][3]));
#pragma unroll
            for (int off = 8; off >= 1; off >>= 1)
                tm = fmaxf(tm, __shfl_xor_sync(0xffffffffu, tm, off));
            float mn = fmaxf(m[r], tm);
            float alpha = __expf(m[r] - mn);
            float rs = 0.f;
#pragma unroll
            for (int c = 0; c < 4; ++c) {
                float p = __expf(s[r][c] - mn);
                sP[(ty + 16 * r) * 68 + tx + 16 * c] = p;
                rs += p;
            }
#pragma unroll
            for (int off = 8; off >= 1; off >>= 1)
                rs += __shfl_xor_sync(0xffffffffu, rs, off);
            l[r] = l[r] * alpha + rs;
            m[r] = mn;
#pragma unroll
            for (int j = 0; j < 8; ++j) o[r][j] *= alpha;
        }
        __syncthreads();

#pragma unroll 4
        for (int j = 0; j < 64; ++j) {
            float4 v0 = *(const float4*)&sV[j * 132 + tx * 4];
            float4 v1 = *(const float4*)&sV[j * 132 + 64 + tx * 4];
#pragma unroll
            for (int r = 0; r < 4; ++r) {
                float p = sP[(ty + 16 * r) * 68 + j];
                o[r][0] += p * v0.x;
                o[r][1] += p * v0.y;
                o[r][2] += p * v0.z;
                o[r][3] += p * v0.w;
                o[r][4] += p * v1.x;
                o[r][5] += p * v1.y;
                o[r][6] += p * v1.z;
                o[r][7] += p * v1.w;
            }
        }
    }

#pragma unroll
    for (int r = 0; r < 4; ++r) {
        float inv = 1.f / l[r];
        int row = qbase + ty + 16 * r;
        float* dst = &g_attn[(rowbase + row) * EMBD + h * HDIM];
        float4 w0, w1;
        w0.x = o[r][0] * inv; w0.y = o[r][1] * inv;
        w0.z = o[r][2] * inv; w0.w = o[r][3] * inv;
        w1.x = o[r][4] * inv; w1.y = o[r][5] * inv;
        w1.z = o[r][6] * inv; w1.w = o[r][7] * inv;
        *(float4*)&dst[tx * 4] = w0;
        *(float4*)&dst[64 + tx * 4] = w1;
    }
}

// ---------------------------------------------------------------------------
// Launch
// ---------------------------------------------------------------------------
extern "C" void kernel_launch(void* const* d_in, const int* in_sizes, int n_in,
                              void* d_out, int out_size)
{
    const float* x  = (const float*)d_in[0];
    const float* Wq = (const float*)d_in[1];
    const float* Wk = (const float*)d_in[2];
    const float* Wv = (const float*)d_in[3];
    const float* Wo = (const float*)d_in[4];

    float *q, *k, *v, *attn;
    cudaGetSymbolAddress((void**)&q, g_q);
    cudaGetSymbolAddress((void**)&k, g_k);
    cudaGetSymbolAddress((void**)&v, g_v);
    cudaGetSymbolAddress((void**)&attn, g_attn);

    cudaFuncSetAttribute(gemm_bf16x3, cudaFuncAttributeMaxDynamicSharedMemorySize,
                         GEMM_SMEM);
    cudaFuncSetAttribute(flash_attn, cudaFuncAttributeMaxDynamicSharedMemorySize,
                         FLASH_SMEM);

    // projections: C = A * W^T  (mma.sync bf16 m16n8k16, bf16x3-compensated)
    gemm_bf16x3<<<dim3(EMBD / 128, MROWS / 128), 256, GEMM_SMEM>>>(x, Wq, q, MROWS, EMBD, EMBD);
    gemm_bf16x3<<<dim3((NGR * HDIM) / 128, MROWS / 128), 256, GEMM_SMEM>>>(x, Wk, k, MROWS, NGR * HDIM, EMBD);
    gemm_bf16x3<<<dim3((NGR * HDIM) / 128, MROWS / 128), 256, GEMM_SMEM>>>(x, Wv, v, MROWS, NGR * HDIM, EMBD);

    // RoPE on q and k
    rope_kernel<<<(MROWS * NHE * 64) / 256, 256>>>(q, NHE);
    rope_kernel<<<(MROWS * NGR * 64) / 256, 256>>>(k, NGR);

    // fused causal attention (fp32 SIMT)
    flash_attn<<<dim3(TT / 64, NHE, BB), 256, FLASH_SMEM>>>();

    // output projection
    gemm_bf16x3<<<dim3(EMBD / 128, MROWS / 128), 256, GEMM_SMEM>>>(attn, Wo, (float*)d_out, MROWS, EMBD, EMBD);
}